// round 9
// baseline (speedup 1.0000x reference)
#include <cuda_runtime.h>

// Problem constants
#define N_    64
#define C_    64
#define T_    300
#define V_    25
#define IC_   16
#define NS_   3

typedef unsigned long long ull;

__device__ __forceinline__ ull dup2(float v) {
    ull r; asm("mov.b64 %0, {%1, %1};" : "=l"(r) : "f"(v)); return r;
}
__device__ __forceinline__ void fma2(ull& acc, ull a, ull b) {
    asm("fma.rn.f32x2 %0, %1, %2, %0;" : "+l"(acc) : "l"(a), "l"(b));
}
__device__ __forceinline__ ull mul2(ull a, ull b) {
    ull d; asm("mul.rn.f32x2 %0, %1, %2;" : "=l"(d) : "l"(a), "l"(b)); return d;
}
__device__ __forceinline__ void unpack2(ull v, float& lo, float& hi) {
    asm("mov.b64 {%0, %1}, %2;" : "=f"(lo), "=f"(hi) : "l"(v));
}

// Fast exp on the FMA pipe (no MUFU). |rel err| ~2e-6.
__device__ __forceinline__ float fastexp(float x) {
    const float L2E = 1.4426950408889634f;
    x = fmaxf(x, -80.0f);
    float t = fmaf(x, L2E, 12582912.0f);
    float k = t - 12582912.0f;
    float f = fmaf(x, L2E, -k);
    float p =              1.3333558146e-3f;
    p = fmaf(p, f, 9.6181291076e-3f);
    p = fmaf(p, f, 5.5504108664e-2f);
    p = fmaf(p, f, 2.4022650696e-1f);
    p = fmaf(p, f, 6.9314718056e-1f);
    p = fmaf(p, f, 1.0f);
    int ik = __float_as_int(t) - 0x4B400000;
    float scale = __int_as_float((ik + 127) << 23);
    return p * scale;
}

// Intermediate M buffer: M[s][n][t][v]
__device__ float g_M[NS_ * N_ * T_ * V_];

// ======================= Kernel A: attention -> M =======================
#define TCA   4
#define COLSA 100
#define NTA   256
#define GRIDA (N_ * (T_ / TCA))   // 4800

struct SmemA {
    float WabT[NS_][64][32];        // 24576 B  [s][c][r] r<16:a_w r>=16:b_w
    float xs[64][COLSA];            // 25600 B
    float CaCb[NS_][32][TCA * 28];  // 43008 B; after logits barrier reused as
                                    //   PmU[s][tc][a][b] = probs (31200 B)
    float colA[NS_][32];
    float absh[NS_][32];
};

__global__ void __launch_bounds__(NTA, 2)
tsagc_attn_kernel(const float* __restrict__ x,
                  const float* __restrict__ A,
                  const float* __restrict__ GA,
                  const float* __restrict__ a_w,
                  const float* __restrict__ a_b,
                  const float* __restrict__ b_w,
                  const float* __restrict__ b_b)
{
    extern __shared__ float smem_raw[];
    SmemA& sm = *reinterpret_cast<SmemA*>(smem_raw);
    const int tid = threadIdx.x;

    // ---- stage weights / constants ----
    for (int idx = tid; idx < NS_ * IC_ * 64; idx += NTA) {
        int c  = idx & 63;
        int ic = (idx >> 6) & 15;
        int s  = idx >> 10;
        sm.WabT[s][c][ic]      = a_w[idx];
        sm.WabT[s][c][16 + ic] = b_w[idx];
    }
    for (int idx = tid; idx < NS_ * IC_; idx += NTA) {
        int s = idx / IC_, ic = idx % IC_;
        sm.absh[s][ic]      = a_b[idx];
        sm.absh[s][16 + ic] = b_b[idx];
    }
    for (int idx = tid; idx < NS_ * V_; idx += NTA) {
        int s = idx / V_, v = idx % V_;
        float acc = 0.f;
        #pragma unroll 5
        for (int a = 0; a < V_; a++) {
            int off = (s * V_ + a) * V_ + v;
            acc += A[off] + GA[off];
        }
        sm.colA[s][v] = acc;
    }
    // zero CaCb pad columns v=25..27 (all s)
    for (int idx = tid; idx < NS_ * 32 * TCA * 3; idx += NTA) {
        int s = idx / (32 * TCA * 3);
        int r = (idx / (TCA * 3)) % 32;
        int q = idx % (TCA * 3);
        sm.CaCb[s][r][(q / 3) * 28 + 25 + (q % 3)] = 0.f;
    }

    // ---- load x chunk ----
    const int n  = blockIdx.x / (T_ / TCA);
    const int t0 = (blockIdx.x % (T_ / TCA)) * TCA;
    const float* xg = x + (n * 64 * T_ + t0) * V_;
    for (int idx = tid; idx < 64 * (COLSA / 4); idx += NTA) {
        int c = idx / (COLSA / 4), q = idx % (COLSA / 4);
        float4 val = *reinterpret_cast<const float4*>(xg + c * (T_ * V_) + q * 4);
        *reinterpret_cast<float4*>(&sm.xs[c][q * 4]) = val;
    }
    __syncthreads();

    // ---- Phase 1 (fused over s): CaCb[s] = Wab[s] @ xs, 4x4 tiles (200 thr) ----
    if (tid < 200) {
        const int rg   = tid / 25;     // 0..7
        const int cg   = tid % 25;     // 0..24
        const int col0 = cg * 4;
        const int r0   = rg * 4;

        int tcv[4], vv[4];
        #pragma unroll
        for (int j = 0; j < 4; j++) {
            int col = col0 + j;
            tcv[j] = col / 25;
            vv[j]  = col - tcv[j] * 25;
        }

        ull acc2[NS_][2][4];   // [s][row-pair][col]
        #pragma unroll
        for (int s = 0; s < NS_; s++)
            #pragma unroll
            for (int k = 0; k < 2; k++)
                #pragma unroll
                for (int j = 0; j < 4; j++) acc2[s][k][j] = 0ull;

        #pragma unroll 2
        for (int c = 0; c < 64; c++) {
            float4 xv = *reinterpret_cast<const float4*>(&sm.xs[c][col0]);
            ull xd[4] = {dup2(xv.x), dup2(xv.y), dup2(xv.z), dup2(xv.w)};
            #pragma unroll
            for (int s = 0; s < NS_; s++) {
                ulonglong2 wp = *reinterpret_cast<const ulonglong2*>(&sm.WabT[s][c][r0]);
                #pragma unroll
                for (int j = 0; j < 4; j++) {
                    fma2(acc2[s][0][j], wp.x, xd[j]);
                    fma2(acc2[s][1][j], wp.y, xd[j]);
                }
            }
        }
        #pragma unroll
        for (int s = 0; s < NS_; s++) {
            #pragma unroll
            for (int k = 0; k < 2; k++) {
                float bA = sm.absh[s][r0 + 2 * k];
                float bB = sm.absh[s][r0 + 2 * k + 1];
                #pragma unroll
                for (int j = 0; j < 4; j++) {
                    float lo, hi;
                    unpack2(acc2[s][k][j], lo, hi);
                    int off = tcv[j] * 28 + vv[j];
                    sm.CaCb[s][r0 + 2 * k][off]     = lo + bA;
                    sm.CaCb[s][r0 + 2 * k + 1][off] = hi + bB;
                }
            }
        }
    }
    __syncthreads();

    // ---- Phase 2a: all 3 subsets concurrently (156 threads, 2 rows each) ----
    float* PmU = &sm.CaCb[0][0][0];   // overlay; valid after logits barrier
    ull lA[13], lB[13];
    int sP = 0, tcP = 0, a0P = 0;
    bool has2 = false;
    if (tid < 156) {
        sP  = tid / 52;
        int q = tid % 52;
        tcP = q / 13;
        a0P = q % 13;
        has2 = (a0P < 12);
        const int a1 = a0P + 13;
        const int tcBase = tcP * 28;
        #pragma unroll
        for (int p = 0; p < 13; p++) { lA[p] = 0ull; lB[p] = 0ull; }
        #pragma unroll 4
        for (int ic = 0; ic < 16; ic++) {
            ull cad0 = dup2(sm.CaCb[sP][ic][tcBase + a0P]);
            ull cad1 = has2 ? dup2(sm.CaCb[sP][ic][tcBase + a1]) : 0ull;
            const ulonglong2* cb =
                reinterpret_cast<const ulonglong2*>(&sm.CaCb[sP][16 + ic][tcBase]);
            #pragma unroll
            for (int q2 = 0; q2 < 6; q2++) {
                ulonglong2 cv = cb[q2];
                fma2(lA[q2 * 2],     cad0, cv.x);
                fma2(lA[q2 * 2 + 1], cad0, cv.y);
                fma2(lB[q2 * 2],     cad1, cv.x);
                fma2(lB[q2 * 2 + 1], cad1, cv.y);
            }
            ulonglong2 cv6 = cb[6];
            fma2(lA[12], cad0, cv6.x);
            fma2(lB[12], cad1, cv6.x);
        }
    }
    __syncthreads();   // all CaCb reads complete; region becomes PmU

    if (tid < 156) {
        // softmax row a0 -> PmU
        {
            float l[26];
            #pragma unroll
            for (int p = 0; p < 13; p++) unpack2(lA[p], l[2 * p], l[2 * p + 1]);
            float mx = -1e30f;
            #pragma unroll
            for (int b = 0; b < 25; b++) { l[b] *= 0.0625f; mx = fmaxf(mx, l[b]); }
            float ssum = 0.f;
            #pragma unroll
            for (int b = 0; b < 25; b++) { float e = fastexp(l[b] - mx); ssum += e; l[b] = e; }
            float inv = 1.f / ssum;
            float* pr = PmU + (((sP * TCA + tcP) * 25 + a0P) * 26);
            #pragma unroll
            for (int b = 0; b < 25; b++) pr[b] = l[b] * inv;
        }
        if (has2) {
            float l[26];
            #pragma unroll
            for (int p = 0; p < 13; p++) unpack2(lB[p], l[2 * p], l[2 * p + 1]);
            float mx = -1e30f;
            #pragma unroll
            for (int b = 0; b < 25; b++) { l[b] *= 0.0625f; mx = fmaxf(mx, l[b]); }
            float ssum = 0.f;
            #pragma unroll
            for (int b = 0; b < 25; b++) { float e = fastexp(l[b] - mx); ssum += e; l[b] = e; }
            float inv = 1.f / ssum;
            float* pr = PmU + (((sP * TCA + tcP) * 25 + (a0P + 13)) * 26);
            #pragma unroll
            for (int b = 0; b < 25; b++) pr[b] = l[b] * inv;
        }
    }
    __syncthreads();

    // ---- Phase 2b: column sums -> g_M (300 items over 150 threads x 2) ----
    if (tid < 150) {
        #pragma unroll
        for (int h = 0; h < 2; h++) {
            int item = tid + h * 150;
            int s    = item / 100;
            int rest = item - s * 100;
            int tc   = rest / 25;
            int b    = rest - tc * 25;
            const float* pb = PmU + ((s * TCA + tc) * 25) * 26 + b;
            float msum = sm.colA[s][b];
            #pragma unroll 5
            for (int a = 0; a < 25; a++) msum += pb[a * 26];
            g_M[((s * N_ + n) * T_ + t0 + tc) * V_ + b] = msum;
        }
    }
}

// ======================= Kernel B: output GEMM (o-split, 8x6 tiles) =======================
#define TCB   12
#define COLSB 300
#define NTB   200
#define GRIDB (N_ * (T_ / TCB) * 2)   // 3200

struct SmemB {
    float GTh[NS_][64][32];    // 24576 B  [s][c][o_local], o-half
    float xs[64][COLSB];       // 76800 B
    float Msm[NS_][COLSB];     // 3600 B
    float scArr[32];
    float shArr[32];
};

__global__ void __launch_bounds__(NTB, 2)
tsagc_out_kernel(const float* __restrict__ x,
                 const float* __restrict__ g_w,
                 const float* __restrict__ g_b,
                 const float* __restrict__ bn_gamma,
                 const float* __restrict__ bn_beta,
                 const float* __restrict__ bn_mean,
                 const float* __restrict__ bn_var,
                 float* __restrict__ out)
{
    extern __shared__ float smem_raw[];
    SmemB& sm = *reinterpret_cast<SmemB*>(smem_raw);
    const int tid = threadIdx.x;

    const int bid    = blockIdx.x;
    const int n      = bid / (2 * (T_ / TCB));
    const int rem    = bid % (2 * (T_ / TCB));
    const int t0     = (rem >> 1) * TCB;
    const int o_base = (rem & 1) * 32;

    // ---- stage GT half (transposed) ----
    for (int idx = tid; idx < NS_ * 64 * 32; idx += NTB) {
        int ol = idx & 31;
        int c  = (idx >> 5) & 63;
        int s  = idx >> 11;
        sm.GTh[s][c][ol] = g_w[(s * 64 + o_base + ol) * 64 + c];
    }
    if (tid < 32) {
        int o = o_base + tid;
        float inv = rsqrtf(bn_var[o] + 1e-5f);
        float scv = bn_gamma[o] * inv;
        sm.scArr[tid] = scv;
        float cb = g_b[o] + g_b[64 + o] + g_b[128 + o];
        sm.shArr[tid] = (cb - bn_mean[o]) * scv + bn_beta[o];
    }

    // ---- load x chunk + M chunk ----
    const float* xg = x + (n * 64 * T_ + t0) * V_;
    for (int idx = tid; idx < 64 * (COLSB / 4); idx += NTB) {
        int c = idx / (COLSB / 4), q = idx % (COLSB / 4);
        float4 val = *reinterpret_cast<const float4*>(xg + c * (T_ * V_) + q * 4);
        *reinterpret_cast<float4*>(&sm.xs[c][q * 4]) = val;
    }
    for (int idx = tid; idx < NS_ * (COLSB / 4); idx += NTB) {
        int s = idx / (COLSB / 4), q = idx % (COLSB / 4);
        float4 val = *reinterpret_cast<const float4*>(
            &g_M[(s * N_ + n) * (T_ * V_) + t0 * V_ + q * 4]);
        *reinterpret_cast<float4*>(&sm.Msm[s][q * 4]) = val;
    }
    __syncthreads();

    // ---- mainloop: 8 rows (4 o-pairs) x 6 cols per thread, fused s ----
    const int rg   = tid / 50;     // 0..3 -> o0 local = rg*8
    const int cg   = tid % 50;     // 0..49
    const int col0 = cg * 6;
    const int o0   = rg * 8;

    ull msd[NS_][6];
    #pragma unroll
    for (int s = 0; s < NS_; s++)
        #pragma unroll
        for (int j = 0; j < 6; j++) msd[s][j] = dup2(sm.Msm[s][col0 + j]);

    ull acc2[4][6];   // [o-pair][col]
    #pragma unroll
    for (int k = 0; k < 4; k++)
        #pragma unroll
        for (int j = 0; j < 6; j++) acc2[k][j] = 0ull;

    #pragma unroll 2
    for (int c = 0; c < 64; c++) {
        const float* xr = &sm.xs[c][col0];
        float2 xv0 = *reinterpret_cast<const float2*>(xr);
        float2 xv1 = *reinterpret_cast<const float2*>(xr + 2);
        float2 xv2 = *reinterpret_cast<const float2*>(xr + 4);
        ull xd[6] = {dup2(xv0.x), dup2(xv0.y), dup2(xv1.x),
                     dup2(xv1.y), dup2(xv2.x), dup2(xv2.y)};
        #pragma unroll
        for (int s = 0; s < NS_; s++) {
            const ulonglong2* gp =
                reinterpret_cast<const ulonglong2*>(&sm.GTh[s][c][o0]);
            ulonglong2 g01 = gp[0];
            ulonglong2 g23 = gp[1];
            #pragma unroll
            for (int j = 0; j < 6; j++) {
                ull xm = mul2(xd[j], msd[s][j]);
                fma2(acc2[0][j], g01.x, xm);
                fma2(acc2[1][j], g01.y, xm);
                fma2(acc2[2][j], g23.x, xm);
                fma2(acc2[3][j], g23.y, xm);
            }
        }
    }

    // ---- epilogue: BN + residual + ReLU ----
    #pragma unroll
    for (int k = 0; k < 4; k++) {
        int oa = o0 + 2 * k;       // local
        int ob = oa + 1;
        float scA = sm.scArr[oa], shA = sm.shArr[oa];
        float scB = sm.scArr[ob], shB = sm.shArr[ob];
        float ra[6], rb[6];
        #pragma unroll
        for (int j = 0; j < 6; j++) unpack2(acc2[k][j], ra[j], rb[j]);
        const float* xrA = &sm.xs[o_base + oa][col0];
        const float* xrB = &sm.xs[o_base + ob][col0];
        float* opA = out + (n * 64 + o_base + oa) * (T_ * V_) + t0 * V_ + col0;
        float* opB = out + (n * 64 + o_base + ob) * (T_ * V_) + t0 * V_ + col0;
        #pragma unroll
        for (int q = 0; q < 3; q++) {
            float2 resA, resB;
            resA.x = fmaxf(ra[2 * q]     * scA + shA + xrA[2 * q],     0.f);
            resA.y = fmaxf(ra[2 * q + 1] * scA + shA + xrA[2 * q + 1], 0.f);
            resB.x = fmaxf(rb[2 * q]     * scB + shB + xrB[2 * q],     0.f);
            resB.y = fmaxf(rb[2 * q + 1] * scB + shB + xrB[2 * q + 1], 0.f);
            *reinterpret_cast<float2*>(opA + 2 * q) = resA;
            *reinterpret_cast<float2*>(opB + 2 * q) = resB;
        }
    }
}

extern "C" void kernel_launch(void* const* d_in, const int* in_sizes, int n_in,
                              void* d_out, int out_size)
{
    const float* x        = (const float*)d_in[0];
    const float* A        = (const float*)d_in[1];
    const float* GA       = (const float*)d_in[2];
    const float* g_w      = (const float*)d_in[3];
    const float* g_b      = (const float*)d_in[4];
    const float* a_w      = (const float*)d_in[5];
    const float* a_b      = (const float*)d_in[6];
    const float* b_w      = (const float*)d_in[7];
    const float* b_b      = (const float*)d_in[8];
    const float* bn_gamma = (const float*)d_in[9];
    const float* bn_beta  = (const float*)d_in[10];
    const float* bn_mean  = (const float*)d_in[11];
    const float* bn_var   = (const float*)d_in[12];
    float* out = (float*)d_out;

    size_t smemA = sizeof(SmemA);
    size_t smemB = sizeof(SmemB);
    cudaFuncSetAttribute(tsagc_attn_kernel,
                         cudaFuncAttributeMaxDynamicSharedMemorySize, (int)smemA);
    cudaFuncSetAttribute(tsagc_out_kernel,
                         cudaFuncAttributeMaxDynamicSharedMemorySize, (int)smemB);

    tsagc_attn_kernel<<<GRIDA, NTA, smemA>>>(x, A, GA, a_w, a_b, b_w, b_b);
    tsagc_out_kernel<<<GRIDB, NTB, smemB>>>(x, g_w, g_b, bn_gamma, bn_beta,
                                            bn_mean, bn_var, out);
}

// round 10
// speedup vs baseline: 1.7797x; 1.7797x over previous
#include <cuda_runtime.h>

// Problem constants
#define N_    64
#define C_    64
#define T_    300
#define V_    25
#define IC_   16
#define NS_   3

typedef unsigned long long ull;

__device__ __forceinline__ ull dup2(float v) {
    ull r; asm("mov.b64 %0, {%1, %1};" : "=l"(r) : "f"(v)); return r;
}
__device__ __forceinline__ void fma2(ull& acc, ull a, ull b) {
    asm("fma.rn.f32x2 %0, %1, %2, %0;" : "+l"(acc) : "l"(a), "l"(b));
}
__device__ __forceinline__ void unpack2(ull v, float& lo, float& hi) {
    asm("mov.b64 {%0, %1}, %2;" : "=f"(lo), "=f"(hi) : "l"(v));
}

// Fast exp on the FMA pipe (no MUFU). |rel err| ~2e-6.
__device__ __forceinline__ float fastexp(float x) {
    const float L2E = 1.4426950408889634f;
    x = fmaxf(x, -80.0f);
    float t = fmaf(x, L2E, 12582912.0f);
    float k = t - 12582912.0f;
    float f = fmaf(x, L2E, -k);
    float p =              1.3333558146e-3f;
    p = fmaf(p, f, 9.6181291076e-3f);
    p = fmaf(p, f, 5.5504108664e-2f);
    p = fmaf(p, f, 2.4022650696e-1f);
    p = fmaf(p, f, 6.9314718056e-1f);
    p = fmaf(p, f, 1.0f);
    int ik = __float_as_int(t) - 0x4B400000;
    float scale = __int_as_float((ik + 127) << 23);
    return p * scale;
}

// Intermediate M buffer: M[s][n][t][v]
__device__ float g_M[NS_ * N_ * T_ * V_];

// ======================= Kernel A: attention -> M =======================
#define TCA   4
#define COLSA 100
#define NTA   384                      // 12 warps = NS_ * TCA
#define GRIDA (N_ * (T_ / TCA))        // 4800

struct SmemA {
    float WabT[NS_][64][32];        // 24576 B  [s][c][r] r<16:a_w r>=16:b_w
    float xs[64][COLSA];            // 25600 B
    float CaCb[NS_][32][TCA * 28];  // 43008 B  [s][r][tc*28+v]
    float colA[NS_][32];
    float absh[NS_][32];
};

__global__ void __launch_bounds__(NTA, 2)
tsagc_attn_kernel(const float* __restrict__ x,
                  const float* __restrict__ A,
                  const float* __restrict__ GA,
                  const float* __restrict__ a_w,
                  const float* __restrict__ a_b,
                  const float* __restrict__ b_w,
                  const float* __restrict__ b_b)
{
    extern __shared__ float smem_raw[];
    SmemA& sm = *reinterpret_cast<SmemA*>(smem_raw);
    const int tid = threadIdx.x;

    // ---- stage weights / constants ----
    for (int idx = tid; idx < NS_ * IC_ * 64; idx += NTA) {
        int c  = idx & 63;
        int ic = (idx >> 6) & 15;
        int s  = idx >> 10;
        sm.WabT[s][c][ic]      = a_w[idx];
        sm.WabT[s][c][16 + ic] = b_w[idx];
    }
    for (int idx = tid; idx < NS_ * IC_; idx += NTA) {
        int s = idx / IC_, ic = idx % IC_;
        sm.absh[s][ic]      = a_b[idx];
        sm.absh[s][16 + ic] = b_b[idx];
    }
    for (int idx = tid; idx < NS_ * V_; idx += NTA) {
        int s = idx / V_, v = idx % V_;
        float acc = 0.f;
        #pragma unroll 5
        for (int a = 0; a < V_; a++) {
            int off = (s * V_ + a) * V_ + v;
            acc += A[off] + GA[off];
        }
        sm.colA[s][v] = acc;
    }
    // zero CaCb pad columns v=25..27 (all s)
    for (int idx = tid; idx < NS_ * 32 * TCA * 3; idx += NTA) {
        int s = idx / (32 * TCA * 3);
        int r = (idx / (TCA * 3)) % 32;
        int q = idx % (TCA * 3);
        sm.CaCb[s][r][(q / 3) * 28 + 25 + (q % 3)] = 0.f;
    }

    // ---- load x chunk ----
    const int n  = blockIdx.x / (T_ / TCA);
    const int t0 = (blockIdx.x % (T_ / TCA)) * TCA;
    const float* xg = x + (n * 64 * T_ + t0) * V_;
    for (int idx = tid; idx < 64 * (COLSA / 4); idx += NTA) {
        int c = idx / (COLSA / 4), q = idx % (COLSA / 4);
        float4 val = *reinterpret_cast<const float4*>(xg + c * (T_ * V_) + q * 4);
        *reinterpret_cast<float4*>(&sm.xs[c][q * 4]) = val;
    }
    __syncthreads();

    // ---- Phase 1 (s-major): CaCb[s] = Wab[s] @ xs, 8 rows x 4 cols (300 thr) ----
    if (tid < 300) {
        const int s1   = tid / 100;          // subset
        const int rem  = tid - s1 * 100;
        const int rg   = rem / 25;           // 0..3 -> r0 = rg*8
        const int cg   = rem % 25;           // 0..24
        const int col0 = cg * 4;
        const int r0   = rg * 8;

        int tcv[4], vv[4];
        #pragma unroll
        for (int j = 0; j < 4; j++) {
            int col = col0 + j;
            tcv[j] = col / 25;
            vv[j]  = col - tcv[j] * 25;
        }

        ull acc2[4][4];   // [row-pair][col]
        #pragma unroll
        for (int k = 0; k < 4; k++)
            #pragma unroll
            for (int j = 0; j < 4; j++) acc2[k][j] = 0ull;

        #pragma unroll 2
        for (int c = 0; c < 64; c++) {
            ulonglong2 wp0 = *reinterpret_cast<const ulonglong2*>(&sm.WabT[s1][c][r0]);
            ulonglong2 wp1 = *reinterpret_cast<const ulonglong2*>(&sm.WabT[s1][c][r0 + 4]);
            float4 xv = *reinterpret_cast<const float4*>(&sm.xs[c][col0]);
            ull xd[4] = {dup2(xv.x), dup2(xv.y), dup2(xv.z), dup2(xv.w)};
            #pragma unroll
            for (int j = 0; j < 4; j++) {
                fma2(acc2[0][j], wp0.x, xd[j]);
                fma2(acc2[1][j], wp0.y, xd[j]);
                fma2(acc2[2][j], wp1.x, xd[j]);
                fma2(acc2[3][j], wp1.y, xd[j]);
            }
        }
        #pragma unroll
        for (int k = 0; k < 4; k++) {
            float bA = sm.absh[s1][r0 + 2 * k];
            float bB = sm.absh[s1][r0 + 2 * k + 1];
            #pragma unroll
            for (int j = 0; j < 4; j++) {
                float lo, hi;
                unpack2(acc2[k][j], lo, hi);
                int off = tcv[j] * 28 + vv[j];
                sm.CaCb[s1][r0 + 2 * k][off]     = lo + bA;
                sm.CaCb[s1][r0 + 2 * k + 1][off] = hi + bB;
            }
        }
    }
    __syncthreads();

    // ---- Phase 2: one warp per (s,tc); lane = softmax row; no barriers ----
    {
        const int wid  = tid >> 5;          // 0..11
        const int lane = tid & 31;
        const int s2   = wid >> 2;          // wid/4
        const int tc   = wid & 3;
        const int a    = (lane < 25) ? lane : 24;   // clamp: valid data, zeroed later
        const int tcBase = tc * 28;

        // logits for row a (f32x2 pairs over b)
        ull l2[13];
        #pragma unroll
        for (int p = 0; p < 13; p++) l2[p] = 0ull;
        #pragma unroll 4
        for (int ic = 0; ic < 16; ic++) {
            ull cad = dup2(sm.CaCb[s2][ic][tcBase + a]);
            const ulonglong2* cb =
                reinterpret_cast<const ulonglong2*>(&sm.CaCb[s2][16 + ic][tcBase]);
            #pragma unroll
            for (int q = 0; q < 6; q++) {
                ulonglong2 cv = cb[q];
                fma2(l2[q * 2],     cad, cv.x);
                fma2(l2[q * 2 + 1], cad, cv.y);
            }
            fma2(l2[12], cad, cb[6].x);
        }
        float l[26];
        #pragma unroll
        for (int p = 0; p < 13; p++) unpack2(l2[p], l[2 * p], l[2 * p + 1]);

        // softmax over b
        float mx = -1e30f;
        #pragma unroll
        for (int b = 0; b < 25; b++) { l[b] *= 0.0625f; mx = fmaxf(mx, l[b]); }
        float ssum = 0.f;
        #pragma unroll
        for (int b = 0; b < 25; b++) { float e = fastexp(l[b] - mx); ssum += e; l[b] = e; }
        float inv = 1.f / ssum;
        if (lane >= 25) inv = 0.f;          // kill duplicate rows before reduce
        #pragma unroll
        for (int b = 0; b < 25; b++) l[b] *= inv;

        // column sums across lanes: butterfly per b, result captured on lane b
        float outv = 0.f;
        #pragma unroll
        for (int b = 0; b < 25; b++) {
            float v = l[b];
            v += __shfl_xor_sync(0xFFFFFFFFu, v, 16);
            v += __shfl_xor_sync(0xFFFFFFFFu, v, 8);
            v += __shfl_xor_sync(0xFFFFFFFFu, v, 4);
            v += __shfl_xor_sync(0xFFFFFFFFu, v, 2);
            v += __shfl_xor_sync(0xFFFFFFFFu, v, 1);
            if (lane == b) outv = v;
        }
        if (lane < 25)
            g_M[((s2 * N_ + n) * T_ + t0 + tc) * V_ + lane] = outv + sm.colA[s2][lane];
    }
}

// ======================= Kernel B: output GEMM (o-split) — R8 config =======================
#define TCB   12
#define COLSB 300
#define NTB   300
#define GRIDB (N_ * (T_ / TCB) * 2)   // 3200

struct SmemB {
    float GTh[NS_][64][32];    // 24576 B  [s][c][o_local], o-half
    float xs[64][COLSB];       // 76800 B
    float Msm[NS_][COLSB];     // 3600 B
    float scArr[32];
    float shArr[32];
};

__global__ void __launch_bounds__(NTB, 2)
tsagc_out_kernel(const float* __restrict__ x,
                 const float* __restrict__ g_w,
                 const float* __restrict__ g_b,
                 const float* __restrict__ bn_gamma,
                 const float* __restrict__ bn_beta,
                 const float* __restrict__ bn_mean,
                 const float* __restrict__ bn_var,
                 float* __restrict__ out)
{
    extern __shared__ float smem_raw[];
    SmemB& sm = *reinterpret_cast<SmemB*>(smem_raw);
    const int tid = threadIdx.x;

    const int bid    = blockIdx.x;
    const int n      = bid / (2 * (T_ / TCB));
    const int rem    = bid % (2 * (T_ / TCB));
    const int t0     = (rem >> 1) * TCB;
    const int o_base = (rem & 1) * 32;

    // ---- stage GT half (transposed) ----
    for (int idx = tid; idx < NS_ * 64 * 32; idx += NTB) {
        int ol = idx & 31;
        int c  = (idx >> 5) & 63;
        int s  = idx >> 11;
        sm.GTh[s][c][ol] = g_w[(s * 64 + o_base + ol) * 64 + c];
    }
    if (tid < 32) {
        int o = o_base + tid;
        float inv = rsqrtf(bn_var[o] + 1e-5f);
        float scv = bn_gamma[o] * inv;
        sm.scArr[tid] = scv;
        float cb = g_b[o] + g_b[64 + o] + g_b[128 + o];
        sm.shArr[tid] = (cb - bn_mean[o]) * scv + bn_beta[o];
    }

    // ---- load x chunk + M chunk ----
    const float* xg = x + (n * 64 * T_ + t0) * V_;
    for (int idx = tid; idx < 64 * (COLSB / 4); idx += NTB) {
        int c = idx / (COLSB / 4), q = idx % (COLSB / 4);
        float4 val = *reinterpret_cast<const float4*>(xg + c * (T_ * V_) + q * 4);
        *reinterpret_cast<float4*>(&sm.xs[c][q * 4]) = val;
    }
    for (int idx = tid; idx < NS_ * (COLSB / 4); idx += NTB) {
        int s = idx / (COLSB / 4), q = idx % (COLSB / 4);
        float4 val = *reinterpret_cast<const float4*>(
            &g_M[(s * N_ + n) * (T_ * V_) + t0 * V_ + q * 4]);
        *reinterpret_cast<float4*>(&sm.Msm[s][q * 4]) = val;
    }
    __syncthreads();

    // ---- mainloop: 8 rows (4 o-pairs) x 4 cols per thread, fused s ----
    const int rg   = tid / 75;     // 0..3 -> o0 local = rg*8
    const int cg   = tid % 75;     // 0..74
    const int col0 = cg * 4;
    const int o0   = rg * 8;

    float ms[NS_][4];
    #pragma unroll
    for (int s = 0; s < NS_; s++)
        #pragma unroll
        for (int j = 0; j < 4; j++) ms[s][j] = sm.Msm[s][col0 + j];

    ull acc2[4][4];   // [o-pair][col]
    #pragma unroll
    for (int k = 0; k < 4; k++)
        #pragma unroll
        for (int j = 0; j < 4; j++) acc2[k][j] = 0ull;

    #pragma unroll 2
    for (int c = 0; c < 64; c++) {
        float4 xv = *reinterpret_cast<const float4*>(&sm.xs[c][col0]);
        float xa[4] = {xv.x, xv.y, xv.z, xv.w};
        #pragma unroll
        for (int s = 0; s < NS_; s++) {
            const ulonglong2* gp =
                reinterpret_cast<const ulonglong2*>(&sm.GTh[s][c][o0]);
            ulonglong2 g01 = gp[0];
            ulonglong2 g23 = gp[1];
            ull xm[4];
            #pragma unroll
            for (int j = 0; j < 4; j++) xm[j] = dup2(xa[j] * ms[s][j]);
            #pragma unroll
            for (int j = 0; j < 4; j++) {
                fma2(acc2[0][j], g01.x, xm[j]);
                fma2(acc2[1][j], g01.y, xm[j]);
                fma2(acc2[2][j], g23.x, xm[j]);
                fma2(acc2[3][j], g23.y, xm[j]);
            }
        }
    }

    // ---- epilogue: BN + residual + ReLU, float4 stores ----
    #pragma unroll
    for (int k = 0; k < 4; k++) {
        int oa = o0 + 2 * k;       // local
        int ob = oa + 1;
        float scA = sm.scArr[oa], shA = sm.shArr[oa];
        float scB = sm.scArr[ob], shB = sm.shArr[ob];
        float ra[4], rb[4];
        #pragma unroll
        for (int j = 0; j < 4; j++) unpack2(acc2[k][j], ra[j], rb[j]);
        float4 xrA = *reinterpret_cast<const float4*>(&sm.xs[o_base + oa][col0]);
        float4 xrB = *reinterpret_cast<const float4*>(&sm.xs[o_base + ob][col0]);
        float4 resA, resB;
        resA.x = fmaxf(ra[0] * scA + shA + xrA.x, 0.f);
        resA.y = fmaxf(ra[1] * scA + shA + xrA.y, 0.f);
        resA.z = fmaxf(ra[2] * scA + shA + xrA.z, 0.f);
        resA.w = fmaxf(ra[3] * scA + shA + xrA.w, 0.f);
        resB.x = fmaxf(rb[0] * scB + shB + xrB.x, 0.f);
        resB.y = fmaxf(rb[1] * scB + shB + xrB.y, 0.f);
        resB.z = fmaxf(rb[2] * scB + shB + xrB.z, 0.f);
        resB.w = fmaxf(rb[3] * scB + shB + xrB.w, 0.f);
        float* opA = out + (n * 64 + o_base + oa) * (T_ * V_) + t0 * V_ + col0;
        float* opB = out + (n * 64 + o_base + ob) * (T_ * V_) + t0 * V_ + col0;
        *reinterpret_cast<float4*>(opA) = resA;
        *reinterpret_cast<float4*>(opB) = resB;
    }
}

extern "C" void kernel_launch(void* const* d_in, const int* in_sizes, int n_in,
                              void* d_out, int out_size)
{
    const float* x        = (const float*)d_in[0];
    const float* A        = (const float*)d_in[1];
    const float* GA       = (const float*)d_in[2];
    const float* g_w      = (const float*)d_in[3];
    const float* g_b      = (const float*)d_in[4];
    const float* a_w      = (const float*)d_in[5];
    const float* a_b      = (const float*)d_in[6];
    const float* b_w      = (const float*)d_in[7];
    const float* b_b      = (const float*)d_in[8];
    const float* bn_gamma = (const float*)d_in[9];
    const float* bn_beta  = (const float*)d_in[10];
    const float* bn_mean  = (const float*)d_in[11];
    const float* bn_var   = (const float*)d_in[12];
    float* out = (float*)d_out;

    size_t smemA = sizeof(SmemA);
    size_t smemB = sizeof(SmemB);
    cudaFuncSetAttribute(tsagc_attn_kernel,
                         cudaFuncAttributeMaxDynamicSharedMemorySize, (int)smemA);
    cudaFuncSetAttribute(tsagc_out_kernel,
                         cudaFuncAttributeMaxDynamicSharedMemorySize, (int)smemB);

    tsagc_attn_kernel<<<GRIDA, NTA, smemA>>>(x, A, GA, a_w, a_b, b_w, b_b);
    tsagc_out_kernel<<<GRIDB, NTB, smemB>>>(x, g_w, g_b, bn_gamma, bn_beta,
                                            bn_mean, bn_var, out);
}

// round 11
// speedup vs baseline: 1.7984x; 1.0105x over previous
#include <cuda_runtime.h>

// Problem constants
#define N_    64
#define C_    64
#define T_    300
#define V_    25
#define IC_   16
#define NS_   3

typedef unsigned long long ull;

__device__ __forceinline__ ull dup2(float v) {
    ull r; asm("mov.b64 %0, {%1, %1};" : "=l"(r) : "f"(v)); return r;
}
__device__ __forceinline__ void fma2(ull& acc, ull a, ull b) {
    asm("fma.rn.f32x2 %0, %1, %2, %0;" : "+l"(acc) : "l"(a), "l"(b));
}
__device__ __forceinline__ void unpack2(ull v, float& lo, float& hi) {
    asm("mov.b64 {%0, %1}, %2;" : "=f"(lo), "=f"(hi) : "l"(v));
}

// Fast exp on the FMA pipe (no MUFU). |rel err| ~2e-6.
__device__ __forceinline__ float fastexp(float x) {
    const float L2E = 1.4426950408889634f;
    x = fmaxf(x, -80.0f);
    float t = fmaf(x, L2E, 12582912.0f);
    float k = t - 12582912.0f;
    float f = fmaf(x, L2E, -k);
    float p =              1.3333558146e-3f;
    p = fmaf(p, f, 9.6181291076e-3f);
    p = fmaf(p, f, 5.5504108664e-2f);
    p = fmaf(p, f, 2.4022650696e-1f);
    p = fmaf(p, f, 6.9314718056e-1f);
    p = fmaf(p, f, 1.0f);
    int ik = __float_as_int(t) - 0x4B400000;
    float scale = __int_as_float((ik + 127) << 23);
    return p * scale;
}

// Intermediate M buffer: M[s][n][t][v]
__device__ float g_M[NS_ * N_ * T_ * V_];

// ======================= Kernel A: attention -> M =======================
#define TCA   4
#define COLSA 100
#define NTA   384                      // 12 warps = NS_ * TCA
#define GRIDA (N_ * (T_ / TCA))        // 4800

struct SmemA {
    float WabT[NS_][64][32];        // 24576 B  [s][c][r] r<16:a_w r>=16:b_w
    float xs[64][COLSA];            // 25600 B
    float CaCb[NS_][32][TCA * 28];  // 43008 B  [s][r][tc*28+v]
    float colA[NS_][32];
    float absh[NS_][32];
};

__global__ void __launch_bounds__(NTA, 2)
tsagc_attn_kernel(const float* __restrict__ x,
                  const float* __restrict__ A,
                  const float* __restrict__ GA,
                  const float* __restrict__ a_w,
                  const float* __restrict__ a_b,
                  const float* __restrict__ b_w,
                  const float* __restrict__ b_b)
{
    extern __shared__ float smem_raw[];
    SmemA& sm = *reinterpret_cast<SmemA*>(smem_raw);
    const int tid = threadIdx.x;

    // ---- stage weights / constants ----
    for (int idx = tid; idx < NS_ * IC_ * 64; idx += NTA) {
        int c  = idx & 63;
        int ic = (idx >> 6) & 15;
        int s  = idx >> 10;
        sm.WabT[s][c][ic]      = a_w[idx];
        sm.WabT[s][c][16 + ic] = b_w[idx];
    }
    for (int idx = tid; idx < NS_ * IC_; idx += NTA) {
        int s = idx / IC_, ic = idx % IC_;
        sm.absh[s][ic]      = a_b[idx];
        sm.absh[s][16 + ic] = b_b[idx];
    }
    for (int idx = tid; idx < NS_ * V_; idx += NTA) {
        int s = idx / V_, v = idx % V_;
        float acc = 0.f;
        #pragma unroll 5
        for (int a = 0; a < V_; a++) {
            int off = (s * V_ + a) * V_ + v;
            acc += A[off] + GA[off];
        }
        sm.colA[s][v] = acc;
    }
    // zero CaCb pad columns v=25..27 (all s)
    for (int idx = tid; idx < NS_ * 32 * TCA * 3; idx += NTA) {
        int s = idx / (32 * TCA * 3);
        int r = (idx / (TCA * 3)) % 32;
        int q = idx % (TCA * 3);
        sm.CaCb[s][r][(q / 3) * 28 + 25 + (q % 3)] = 0.f;
    }

    // ---- load x chunk ----
    const int n  = blockIdx.x / (T_ / TCA);
    const int t0 = (blockIdx.x % (T_ / TCA)) * TCA;
    const float* xg = x + (n * 64 * T_ + t0) * V_;
    for (int idx = tid; idx < 64 * (COLSA / 4); idx += NTA) {
        int c = idx / (COLSA / 4), q = idx % (COLSA / 4);
        float4 val = *reinterpret_cast<const float4*>(xg + c * (T_ * V_) + q * 4);
        *reinterpret_cast<float4*>(&sm.xs[c][q * 4]) = val;
    }
    __syncthreads();

    // ---- Phase 1 (s-major): CaCb[s] = Wab[s] @ xs, 8 rows x 4 cols (300 thr) ----
    if (tid < 300) {
        const int s1   = tid / 100;          // subset
        const int rem  = tid - s1 * 100;
        const int rg   = rem / 25;           // 0..3 -> r0 = rg*8
        const int cg   = rem % 25;           // 0..24
        const int col0 = cg * 4;
        const int r0   = rg * 8;

        int tcv[4], vv[4];
        #pragma unroll
        for (int j = 0; j < 4; j++) {
            int col = col0 + j;
            tcv[j] = col / 25;
            vv[j]  = col - tcv[j] * 25;
        }

        ull acc2[4][4];   // [row-pair][col]
        #pragma unroll
        for (int k = 0; k < 4; k++)
            #pragma unroll
            for (int j = 0; j < 4; j++) acc2[k][j] = 0ull;

        #pragma unroll 2
        for (int c = 0; c < 64; c++) {
            ulonglong2 wp0 = *reinterpret_cast<const ulonglong2*>(&sm.WabT[s1][c][r0]);
            ulonglong2 wp1 = *reinterpret_cast<const ulonglong2*>(&sm.WabT[s1][c][r0 + 4]);
            float4 xv = *reinterpret_cast<const float4*>(&sm.xs[c][col0]);
            ull xd[4] = {dup2(xv.x), dup2(xv.y), dup2(xv.z), dup2(xv.w)};
            #pragma unroll
            for (int j = 0; j < 4; j++) {
                fma2(acc2[0][j], wp0.x, xd[j]);
                fma2(acc2[1][j], wp0.y, xd[j]);
                fma2(acc2[2][j], wp1.x, xd[j]);
                fma2(acc2[3][j], wp1.y, xd[j]);
            }
        }
        #pragma unroll
        for (int k = 0; k < 4; k++) {
            float bA = sm.absh[s1][r0 + 2 * k];
            float bB = sm.absh[s1][r0 + 2 * k + 1];
            #pragma unroll
            for (int j = 0; j < 4; j++) {
                float lo, hi;
                unpack2(acc2[k][j], lo, hi);
                int off = tcv[j] * 28 + vv[j];
                sm.CaCb[s1][r0 + 2 * k][off]     = lo + bA;
                sm.CaCb[s1][r0 + 2 * k + 1][off] = hi + bB;
            }
        }
    }
    __syncthreads();

    // ---- Phase 2: one warp per (s,tc); 5x5 lane grid; no barriers ----
    {
        const int wid  = tid >> 5;          // 0..11
        const int lane = tid & 31;
        const int s2   = wid >> 2;          // wid/4
        const int tc   = wid & 3;
        const int lv   = (lane < 25) ? lane : 0;   // dead lanes mirror lane 0
        const int cg   = lv / 5;            // column group (b)
        const int rg   = lv % 5;            // row group (a)
        const int a0   = rg * 5;
        const int b0   = cg * 5;
        const int tcBase = tc * 28;

        // 5x5 logit block: S[i][j] = sum_ic Ca[ic][a0+i] * Cb[ic][b0+j]
        float S[5][5];
        #pragma unroll
        for (int i = 0; i < 5; i++)
            #pragma unroll
            for (int j = 0; j < 5; j++) S[i][j] = 0.f;

        #pragma unroll 4
        for (int ic = 0; ic < 16; ic++) {
            float ca[5], cb[5];
            #pragma unroll
            for (int i = 0; i < 5; i++)
                ca[i] = sm.CaCb[s2][ic][tcBase + a0 + i];
            #pragma unroll
            for (int j = 0; j < 5; j++)
                cb[j] = sm.CaCb[s2][16 + ic][tcBase + b0 + j];
            #pragma unroll
            for (int i = 0; i < 5; i++)
                #pragma unroll
                for (int j = 0; j < 5; j++) S[i][j] += ca[i] * cb[j];
        }

        // scale + row max (local, then across the 5 cg-lanes sharing rg)
        float rmax[5];
        #pragma unroll
        for (int i = 0; i < 5; i++) {
            float m = -1e30f;
            #pragma unroll
            for (int j = 0; j < 5; j++) { S[i][j] *= 0.0625f; m = fmaxf(m, S[i][j]); }
            rmax[i] = m;
        }
        #pragma unroll
        for (int k = 1; k < 5; k++) {
            int src = ((cg + k) % 5) * 5 + rg;
            #pragma unroll
            for (int i = 0; i < 5; i++)
                rmax[i] = fmaxf(rmax[i], __shfl_sync(0xFFFFFFFFu, rmax[i], src));
        }

        // exp + row sum
        float rsum[5];
        #pragma unroll
        for (int i = 0; i < 5; i++) {
            float ssum = 0.f;
            #pragma unroll
            for (int j = 0; j < 5; j++) {
                float e = fastexp(S[i][j] - rmax[i]);
                S[i][j] = e;
                ssum += e;
            }
            rsum[i] = ssum;
        }
        #pragma unroll
        for (int k = 1; k < 5; k++) {
            int src = ((cg + k) % 5) * 5 + rg;
            #pragma unroll
            for (int i = 0; i < 5; i++)
                rsum[i] += __shfl_sync(0xFFFFFFFFu, rsum[i], src);
        }

        // normalize + local column sums over the 5 rows
        float colS[5];
        #pragma unroll
        for (int j = 0; j < 5; j++) colS[j] = 0.f;
        #pragma unroll
        for (int i = 0; i < 5; i++) {
            float rinv = 1.f / rsum[i];
            #pragma unroll
            for (int j = 0; j < 5; j++) colS[j] += S[i][j] * rinv;
        }
        // reduce column sums across the 5 rg-lanes sharing cg
        #pragma unroll
        for (int k = 1; k < 5; k++) {
            int src = cg * 5 + (rg + k) % 5;
            #pragma unroll
            for (int j = 0; j < 5; j++)
                colS[j] += __shfl_sync(0xFFFFFFFFu, colS[j], src);
        }

        if (lane < 25 && rg == 0) {
            float* mp = &g_M[((s2 * N_ + n) * T_ + t0 + tc) * V_ + b0];
            #pragma unroll
            for (int j = 0; j < 5; j++)
                mp[j] = colS[j] + sm.colA[s2][b0 + j];
        }
    }
}

// ======================= Kernel B: output GEMM (o-split) — R8/R10 config =======================
#define TCB   12
#define COLSB 300
#define NTB   300
#define GRIDB (N_ * (T_ / TCB) * 2)   // 3200

struct SmemB {
    float GTh[NS_][64][32];    // 24576 B  [s][c][o_local], o-half
    float xs[64][COLSB];       // 76800 B
    float Msm[NS_][COLSB];     // 3600 B
    float scArr[32];
    float shArr[32];
};

__global__ void __launch_bounds__(NTB, 2)
tsagc_out_kernel(const float* __restrict__ x,
                 const float* __restrict__ g_w,
                 const float* __restrict__ g_b,
                 const float* __restrict__ bn_gamma,
                 const float* __restrict__ bn_beta,
                 const float* __restrict__ bn_mean,
                 const float* __restrict__ bn_var,
                 float* __restrict__ out)
{
    extern __shared__ float smem_raw[];
    SmemB& sm = *reinterpret_cast<SmemB*>(smem_raw);
    const int tid = threadIdx.x;

    const int bid    = blockIdx.x;
    const int n      = bid / (2 * (T_ / TCB));
    const int rem    = bid % (2 * (T_ / TCB));
    const int t0     = (rem >> 1) * TCB;
    const int o_base = (rem & 1) * 32;

    // ---- stage GT half (transposed) ----
    for (int idx = tid; idx < NS_ * 64 * 32; idx += NTB) {
        int ol = idx & 31;
        int c  = (idx >> 5) & 63;
        int s  = idx >> 11;
        sm.GTh[s][c][ol] = g_w[(s * 64 + o_base + ol) * 64 + c];
    }
    if (tid < 32) {
        int o = o_base + tid;
        float inv = rsqrtf(bn_var[o] + 1e-5f);
        float scv = bn_gamma[o] * inv;
        sm.scArr[tid] = scv;
        float cb = g_b[o] + g_b[64 + o] + g_b[128 + o];
        sm.shArr[tid] = (cb - bn_mean[o]) * scv + bn_beta[o];
    }

    // ---- load x chunk + M chunk ----
    const float* xg = x + (n * 64 * T_ + t0) * V_;
    for (int idx = tid; idx < 64 * (COLSB / 4); idx += NTB) {
        int c = idx / (COLSB / 4), q = idx % (COLSB / 4);
        float4 val = *reinterpret_cast<const float4*>(xg + c * (T_ * V_) + q * 4);
        *reinterpret_cast<float4*>(&sm.xs[c][q * 4]) = val;
    }
    for (int idx = tid; idx < NS_ * (COLSB / 4); idx += NTB) {
        int s = idx / (COLSB / 4), q = idx % (COLSB / 4);
        float4 val = *reinterpret_cast<const float4*>(
            &g_M[(s * N_ + n) * (T_ * V_) + t0 * V_ + q * 4]);
        *reinterpret_cast<float4*>(&sm.Msm[s][q * 4]) = val;
    }
    __syncthreads();

    // ---- mainloop: 8 rows (4 o-pairs) x 4 cols per thread, fused s ----
    const int rg   = tid / 75;     // 0..3 -> o0 local = rg*8
    const int cg   = tid % 75;     // 0..74
    const int col0 = cg * 4;
    const int o0   = rg * 8;

    float ms[NS_][4];
    #pragma unroll
    for (int s = 0; s < NS_; s++)
        #pragma unroll
        for (int j = 0; j < 4; j++) ms[s][j] = sm.Msm[s][col0 + j];

    ull acc2[4][4];   // [o-pair][col]
    #pragma unroll
    for (int k = 0; k < 4; k++)
        #pragma unroll
        for (int j = 0; j < 4; j++) acc2[k][j] = 0ull;

    #pragma unroll 2
    for (int c = 0; c < 64; c++) {
        float4 xv = *reinterpret_cast<const float4*>(&sm.xs[c][col0]);
        float xa[4] = {xv.x, xv.y, xv.z, xv.w};
        #pragma unroll
        for (int s = 0; s < NS_; s++) {
            const ulonglong2* gp =
                reinterpret_cast<const ulonglong2*>(&sm.GTh[s][c][o0]);
            ulonglong2 g01 = gp[0];
            ulonglong2 g23 = gp[1];
            ull xm[4];
            #pragma unroll
            for (int j = 0; j < 4; j++) xm[j] = dup2(xa[j] * ms[s][j]);
            #pragma unroll
            for (int j = 0; j < 4; j++) {
                fma2(acc2[0][j], g01.x, xm[j]);
                fma2(acc2[1][j], g01.y, xm[j]);
                fma2(acc2[2][j], g23.x, xm[j]);
                fma2(acc2[3][j], g23.y, xm[j]);
            }
        }
    }

    // ---- epilogue: BN + residual + ReLU, float4 stores ----
    #pragma unroll
    for (int k = 0; k < 4; k++) {
        int oa = o0 + 2 * k;       // local
        int ob = oa + 1;
        float scA = sm.scArr[oa], shA = sm.shArr[oa];
        float scB = sm.scArr[ob], shB = sm.shArr[ob];
        float ra[4], rb[4];
        #pragma unroll
        for (int j = 0; j < 4; j++) unpack2(acc2[k][j], ra[j], rb[j]);
        float4 xrA = *reinterpret_cast<const float4*>(&sm.xs[o_base + oa][col0]);
        float4 xrB = *reinterpret_cast<const float4*>(&sm.xs[o_base + ob][col0]);
        float4 resA, resB;
        resA.x = fmaxf(ra[0] * scA + shA + xrA.x, 0.f);
        resA.y = fmaxf(ra[1] * scA + shA + xrA.y, 0.f);
        resA.z = fmaxf(ra[2] * scA + shA + xrA.z, 0.f);
        resA.w = fmaxf(ra[3] * scA + shA + xrA.w, 0.f);
        resB.x = fmaxf(rb[0] * scB + shB + xrB.x, 0.f);
        resB.y = fmaxf(rb[1] * scB + shB + xrB.y, 0.f);
        resB.z = fmaxf(rb[2] * scB + shB + xrB.z, 0.f);
        resB.w = fmaxf(rb[3] * scB + shB + xrB.w, 0.f);
        float* opA = out + (n * 64 + o_base + oa) * (T_ * V_) + t0 * V_ + col0;
        float* opB = out + (n * 64 + o_base + ob) * (T_ * V_) + t0 * V_ + col0;
        *reinterpret_cast<float4*>(opA) = resA;
        *reinterpret_cast<float4*>(opB) = resB;
    }
}

extern "C" void kernel_launch(void* const* d_in, const int* in_sizes, int n_in,
                              void* d_out, int out_size)
{
    const float* x        = (const float*)d_in[0];
    const float* A        = (const float*)d_in[1];
    const float* GA       = (const float*)d_in[2];
    const float* g_w      = (const float*)d_in[3];
    const float* g_b      = (const float*)d_in[4];
    const float* a_w      = (const float*)d_in[5];
    const float* a_b      = (const float*)d_in[6];
    const float* b_w      = (const float*)d_in[7];
    const float* b_b      = (const float*)d_in[8];
    const float* bn_gamma = (const float*)d_in[9];
    const float* bn_beta  = (const float*)d_in[10];
    const float* bn_mean  = (const float*)d_in[11];
    const float* bn_var   = (const float*)d_in[12];
    float* out = (float*)d_out;

    size_t smemA = sizeof(SmemA);
    size_t smemB = sizeof(SmemB);
    cudaFuncSetAttribute(tsagc_attn_kernel,
                         cudaFuncAttributeMaxDynamicSharedMemorySize, (int)smemA);
    cudaFuncSetAttribute(tsagc_out_kernel,
                         cudaFuncAttributeMaxDynamicSharedMemorySize, (int)smemB);

    tsagc_attn_kernel<<<GRIDA, NTA, smemA>>>(x, A, GA, a_w, a_b, b_w, b_b);
    tsagc_out_kernel<<<GRIDB, NTB, smemB>>>(x, g_w, g_b, bn_gamma, bn_beta,
                                            bn_mean, bn_var, out);
}

// round 12
// speedup vs baseline: 1.9000x; 1.0565x over previous
#include <cuda_runtime.h>

// Problem constants
#define N_    64
#define C_    64
#define T_    300
#define V_    25
#define IC_   16
#define NS_   3

typedef unsigned long long ull;

__device__ __forceinline__ ull dup2(float v) {
    ull r; asm("mov.b64 %0, {%1, %1};" : "=l"(r) : "f"(v)); return r;
}
__device__ __forceinline__ void fma2(ull& acc, ull a, ull b) {
    asm("fma.rn.f32x2 %0, %1, %2, %0;" : "+l"(acc) : "l"(a), "l"(b));
}
__device__ __forceinline__ void unpack2(ull v, float& lo, float& hi) {
    asm("mov.b64 {%0, %1}, %2;" : "=f"(lo), "=f"(hi) : "l"(v));
}

// Fast exp on the FMA pipe (no MUFU). |rel err| ~2e-6.
__device__ __forceinline__ float fastexp(float x) {
    const float L2E = 1.4426950408889634f;
    x = fmaxf(x, -80.0f);
    float t = fmaf(x, L2E, 12582912.0f);
    float k = t - 12582912.0f;
    float f = fmaf(x, L2E, -k);
    float p =              1.3333558146e-3f;
    p = fmaf(p, f, 9.6181291076e-3f);
    p = fmaf(p, f, 5.5504108664e-2f);
    p = fmaf(p, f, 2.4022650696e-1f);
    p = fmaf(p, f, 6.9314718056e-1f);
    p = fmaf(p, f, 1.0f);
    int ik = __float_as_int(t) - 0x4B400000;
    float scale = __int_as_float((ik + 127) << 23);
    return p * scale;
}

// Intermediate M buffer: M[s][n][t][v]
__device__ float g_M[NS_ * N_ * T_ * V_];

// ======================= Kernel A: attention -> M (persistent) =======================
#define TCA     4
#define COLSA   100
#define NTA     384                      // 12 warps = NS_ * TCA
#define NCHUNKA (N_ * (T_ / TCA))        // 4800
#define GRIDA_P 296                      // one wave: 148 SMs x 2

struct SmemA {
    float WabT[NS_][64][32];        // 24576 B  [s][c][r] r<16:a_w r>=16:b_w
    float xs[64][COLSA];            // 25600 B
    float CaCb[NS_][32][TCA * 28];  // 43008 B  [s][r][tc*28+v]
    float colA[NS_][32];
    float absh[NS_][32];
};

__global__ void __launch_bounds__(NTA, 2)
tsagc_attn_kernel(const float* __restrict__ x,
                  const float* __restrict__ A,
                  const float* __restrict__ GA,
                  const float* __restrict__ a_w,
                  const float* __restrict__ a_b,
                  const float* __restrict__ b_w,
                  const float* __restrict__ b_b)
{
    extern __shared__ float smem_raw[];
    SmemA& sm = *reinterpret_cast<SmemA*>(smem_raw);
    const int tid = threadIdx.x;

    // ---- stage weights / constants ONCE ----
    for (int idx = tid; idx < NS_ * IC_ * 64; idx += NTA) {
        int c  = idx & 63;
        int ic = (idx >> 6) & 15;
        int s  = idx >> 10;
        sm.WabT[s][c][ic]      = a_w[idx];
        sm.WabT[s][c][16 + ic] = b_w[idx];
    }
    for (int idx = tid; idx < NS_ * IC_; idx += NTA) {
        int s = idx / IC_, ic = idx % IC_;
        sm.absh[s][ic]      = a_b[idx];
        sm.absh[s][16 + ic] = b_b[idx];
    }
    for (int idx = tid; idx < NS_ * V_; idx += NTA) {
        int s = idx / V_, v = idx % V_;
        float acc = 0.f;
        #pragma unroll 5
        for (int a = 0; a < V_; a++) {
            int off = (s * V_ + a) * V_ + v;
            acc += A[off] + GA[off];
        }
        sm.colA[s][v] = acc;
    }
    // zero CaCb pad columns v=25..27 (all s) — phase 1 never overwrites them
    for (int idx = tid; idx < NS_ * 32 * TCA * 3; idx += NTA) {
        int s = idx / (32 * TCA * 3);
        int r = (idx / (TCA * 3)) % 32;
        int q = idx % (TCA * 3);
        sm.CaCb[s][r][(q / 3) * 28 + 25 + (q % 3)] = 0.f;
    }

    // thread mappings (chunk-invariant)
    const int s1p   = (tid < 300) ? tid / 100 : 0;
    const int rem1  = (tid < 300) ? tid - s1p * 100 : 0;
    const int rg1   = rem1 / 25;
    const int cg1   = rem1 % 25;
    const int col0  = cg1 * 4;
    const int r0    = rg1 * 8;
    int tcv[4], vv[4];
    #pragma unroll
    for (int j = 0; j < 4; j++) {
        int col = col0 + j;
        tcv[j] = col / 25;
        vv[j]  = col - tcv[j] * 25;
    }
    const int wid  = tid >> 5;
    const int lane = tid & 31;
    const int s2   = wid >> 2;
    const int tc2  = wid & 3;
    const int lv   = (lane < 25) ? lane : 0;
    const int cg2  = lv / 5;
    const int rg2  = lv % 5;
    const int a0   = rg2 * 5;
    const int b0   = cg2 * 5;
    const int tcBase2 = tc2 * 28;

    for (int chunk = blockIdx.x; chunk < NCHUNKA; chunk += GRIDA_P) {
        const int n  = chunk / (T_ / TCA);
        const int t0 = (chunk % (T_ / TCA)) * TCA;

        __syncthreads();   // staging done / previous chunk's phase-2 reads done

        // ---- load x chunk ----
        const float* xg = x + (n * 64 * T_ + t0) * V_;
        for (int idx = tid; idx < 64 * (COLSA / 4); idx += NTA) {
            int c = idx / (COLSA / 4), q = idx % (COLSA / 4);
            float4 val = *reinterpret_cast<const float4*>(xg + c * (T_ * V_) + q * 4);
            *reinterpret_cast<float4*>(&sm.xs[c][q * 4]) = val;
        }
        __syncthreads();

        // ---- Phase 1 (s-major): CaCb[s] = Wab[s] @ xs, 8 rows x 4 cols (300 thr) ----
        if (tid < 300) {
            ull acc2[4][4];   // [row-pair][col]
            #pragma unroll
            for (int k = 0; k < 4; k++)
                #pragma unroll
                for (int j = 0; j < 4; j++) acc2[k][j] = 0ull;

            #pragma unroll 2
            for (int c = 0; c < 64; c++) {
                ulonglong2 wp0 = *reinterpret_cast<const ulonglong2*>(&sm.WabT[s1p][c][r0]);
                ulonglong2 wp1 = *reinterpret_cast<const ulonglong2*>(&sm.WabT[s1p][c][r0 + 4]);
                float4 xv = *reinterpret_cast<const float4*>(&sm.xs[c][col0]);
                ull xd[4] = {dup2(xv.x), dup2(xv.y), dup2(xv.z), dup2(xv.w)};
                #pragma unroll
                for (int j = 0; j < 4; j++) {
                    fma2(acc2[0][j], wp0.x, xd[j]);
                    fma2(acc2[1][j], wp0.y, xd[j]);
                    fma2(acc2[2][j], wp1.x, xd[j]);
                    fma2(acc2[3][j], wp1.y, xd[j]);
                }
            }
            #pragma unroll
            for (int k = 0; k < 4; k++) {
                float bA = sm.absh[s1p][r0 + 2 * k];
                float bB = sm.absh[s1p][r0 + 2 * k + 1];
                #pragma unroll
                for (int j = 0; j < 4; j++) {
                    float lo, hi;
                    unpack2(acc2[k][j], lo, hi);
                    int off = tcv[j] * 28 + vv[j];
                    sm.CaCb[s1p][r0 + 2 * k][off]     = lo + bA;
                    sm.CaCb[s1p][r0 + 2 * k + 1][off] = hi + bB;
                }
            }
        }
        __syncthreads();

        // ---- Phase 2: one warp per (s,tc); 5x5 lane grid; no barriers ----
        {
            float S[5][5];
            #pragma unroll
            for (int i = 0; i < 5; i++)
                #pragma unroll
                for (int j = 0; j < 5; j++) S[i][j] = 0.f;

            #pragma unroll 4
            for (int ic = 0; ic < 16; ic++) {
                float ca[5], cb[5];
                #pragma unroll
                for (int i = 0; i < 5; i++)
                    ca[i] = sm.CaCb[s2][ic][tcBase2 + a0 + i];
                #pragma unroll
                for (int j = 0; j < 5; j++)
                    cb[j] = sm.CaCb[s2][16 + ic][tcBase2 + b0 + j];
                #pragma unroll
                for (int i = 0; i < 5; i++)
                    #pragma unroll
                    for (int j = 0; j < 5; j++) S[i][j] += ca[i] * cb[j];
            }

            float rmax[5];
            #pragma unroll
            for (int i = 0; i < 5; i++) {
                float m = -1e30f;
                #pragma unroll
                for (int j = 0; j < 5; j++) { S[i][j] *= 0.0625f; m = fmaxf(m, S[i][j]); }
                rmax[i] = m;
            }
            #pragma unroll
            for (int k = 1; k < 5; k++) {
                int src = ((cg2 + k) % 5) * 5 + rg2;
                #pragma unroll
                for (int i = 0; i < 5; i++)
                    rmax[i] = fmaxf(rmax[i], __shfl_sync(0xFFFFFFFFu, rmax[i], src));
            }

            float rsum[5];
            #pragma unroll
            for (int i = 0; i < 5; i++) {
                float ssum = 0.f;
                #pragma unroll
                for (int j = 0; j < 5; j++) {
                    float e = fastexp(S[i][j] - rmax[i]);
                    S[i][j] = e;
                    ssum += e;
                }
                rsum[i] = ssum;
            }
            #pragma unroll
            for (int k = 1; k < 5; k++) {
                int src = ((cg2 + k) % 5) * 5 + rg2;
                #pragma unroll
                for (int i = 0; i < 5; i++)
                    rsum[i] += __shfl_sync(0xFFFFFFFFu, rsum[i], src);
            }

            float colS[5];
            #pragma unroll
            for (int j = 0; j < 5; j++) colS[j] = 0.f;
            #pragma unroll
            for (int i = 0; i < 5; i++) {
                float rinv = 1.f / rsum[i];
                #pragma unroll
                for (int j = 0; j < 5; j++) colS[j] += S[i][j] * rinv;
            }
            #pragma unroll
            for (int k = 1; k < 5; k++) {
                int src = cg2 * 5 + (rg2 + k) % 5;
                #pragma unroll
                for (int j = 0; j < 5; j++)
                    colS[j] += __shfl_sync(0xFFFFFFFFu, colS[j], src);
            }

            if (lane < 25 && rg2 == 0) {
                float* mp = &g_M[((s2 * N_ + n) * T_ + t0 + tc2) * V_ + b0];
                #pragma unroll
                for (int j = 0; j < 5; j++)
                    mp[j] = colS[j] + sm.colA[s2][b0 + j];
            }
        }
    }
}

// ======================= Kernel B: output GEMM (o-split, persistent) =======================
#define TCB     12
#define COLSB   300
#define NTB     300
#define NCHUNKB (N_ * (T_ / TCB) * 2)   // 3200
#define GRIDB_P 296                     // one wave: 148 SMs x 2

struct SmemB {
    float GTh[NS_][64][32];    // 24576 B  [s][c][o_local], o-half (fixed per block? no: both halves)
    float GTh2[NS_][64][32];   // 24576 B  second o-half
    float xs[64][COLSB];       // 76800 B
    float Msm[NS_][COLSB];     // 3600 B
    float scArr[64];
    float shArr[64];
};

__global__ void __launch_bounds__(NTB, 1)
tsagc_out_kernel(const float* __restrict__ x,
                 const float* __restrict__ g_w,
                 const float* __restrict__ g_b,
                 const float* __restrict__ bn_gamma,
                 const float* __restrict__ bn_beta,
                 const float* __restrict__ bn_mean,
                 const float* __restrict__ bn_var,
                 float* __restrict__ out)
{
    extern __shared__ float smem_raw[];
    SmemB& sm = *reinterpret_cast<SmemB*>(smem_raw);
    const int tid = threadIdx.x;

    // ---- stage BOTH GT halves + BN constants ONCE ----
    for (int idx = tid; idx < NS_ * 64 * 64; idx += NTB) {
        int o = idx & 63;
        int c = (idx >> 6) & 63;
        int s = idx >> 12;
        float v = g_w[(s * 64 + o) * 64 + c];
        if (o < 32) sm.GTh[s][c][o] = v;
        else        sm.GTh2[s][c][o - 32] = v;
    }
    if (tid < 64) {
        float inv = rsqrtf(bn_var[tid] + 1e-5f);
        float scv = bn_gamma[tid] * inv;
        sm.scArr[tid] = scv;
        float cb = g_b[tid] + g_b[64 + tid] + g_b[128 + tid];
        sm.shArr[tid] = (cb - bn_mean[tid]) * scv + bn_beta[tid];
    }

    // chunk-invariant thread mapping
    const int rg   = tid / 75;     // 0..3 -> o0 local = rg*8
    const int cg   = tid % 75;     // 0..74
    const int col0 = cg * 4;
    const int o0   = rg * 8;

    for (int chunk = blockIdx.x; chunk < NCHUNKB; chunk += GRIDB_P) {
        const int n      = chunk / (2 * (T_ / TCB));
        const int rem    = chunk % (2 * (T_ / TCB));
        const int t0     = (rem >> 1) * TCB;
        const int o_base = (rem & 1) * 32;
        const float (*GT)[64][32] = (rem & 1) ? sm.GTh2 : sm.GTh;

        __syncthreads();   // staging done / previous epilogue xs reads done

        // ---- load x chunk + M chunk ----
        const float* xg = x + (n * 64 * T_ + t0) * V_;
        for (int idx = tid; idx < 64 * (COLSB / 4); idx += NTB) {
            int c = idx / (COLSB / 4), q = idx % (COLSB / 4);
            float4 val = *reinterpret_cast<const float4*>(xg + c * (T_ * V_) + q * 4);
            *reinterpret_cast<float4*>(&sm.xs[c][q * 4]) = val;
        }
        for (int idx = tid; idx < NS_ * (COLSB / 4); idx += NTB) {
            int s = idx / (COLSB / 4), q = idx % (COLSB / 4);
            float4 val = *reinterpret_cast<const float4*>(
                &g_M[(s * N_ + n) * (T_ * V_) + t0 * V_ + q * 4]);
            *reinterpret_cast<float4*>(&sm.Msm[s][q * 4]) = val;
        }
        __syncthreads();

        // ---- mainloop: 8 rows (4 o-pairs) x 4 cols per thread, fused s ----
        float ms[NS_][4];
        #pragma unroll
        for (int s = 0; s < NS_; s++)
            #pragma unroll
            for (int j = 0; j < 4; j++) ms[s][j] = sm.Msm[s][col0 + j];

        ull acc2[4][4];   // [o-pair][col]
        #pragma unroll
        for (int k = 0; k < 4; k++)
            #pragma unroll
            for (int j = 0; j < 4; j++) acc2[k][j] = 0ull;

        #pragma unroll 2
        for (int c = 0; c < 64; c++) {
            float4 xv = *reinterpret_cast<const float4*>(&sm.xs[c][col0]);
            float xa[4] = {xv.x, xv.y, xv.z, xv.w};
            #pragma unroll
            for (int s = 0; s < NS_; s++) {
                const ulonglong2* gp =
                    reinterpret_cast<const ulonglong2*>(&GT[s][c][o0]);
                ulonglong2 g01 = gp[0];
                ulonglong2 g23 = gp[1];
                ull xm[4];
                #pragma unroll
                for (int j = 0; j < 4; j++) xm[j] = dup2(xa[j] * ms[s][j]);
                #pragma unroll
                for (int j = 0; j < 4; j++) {
                    fma2(acc2[0][j], g01.x, xm[j]);
                    fma2(acc2[1][j], g01.y, xm[j]);
                    fma2(acc2[2][j], g23.x, xm[j]);
                    fma2(acc2[3][j], g23.y, xm[j]);
                }
            }
        }

        // ---- epilogue: BN + residual + ReLU, float4 stores ----
        #pragma unroll
        for (int k = 0; k < 4; k++) {
            int oa = o_base + o0 + 2 * k;   // global o
            int ob = oa + 1;
            float scA = sm.scArr[oa], shA = sm.shArr[oa];
            float scB = sm.scArr[ob], shB = sm.shArr[ob];
            float ra[4], rb[4];
            #pragma unroll
            for (int j = 0; j < 4; j++) unpack2(acc2[k][j], ra[j], rb[j]);
            float4 xrA = *reinterpret_cast<const float4*>(&sm.xs[oa][col0]);
            float4 xrB = *reinterpret_cast<const float4*>(&sm.xs[ob][col0]);
            float4 resA, resB;
            resA.x = fmaxf(ra[0] * scA + shA + xrA.x, 0.f);
            resA.y = fmaxf(ra[1] * scA + shA + xrA.y, 0.f);
            resA.z = fmaxf(ra[2] * scA + shA + xrA.z, 0.f);
            resA.w = fmaxf(ra[3] * scA + shA + xrA.w, 0.f);
            resB.x = fmaxf(rb[0] * scB + shB + xrB.x, 0.f);
            resB.y = fmaxf(rb[1] * scB + shB + xrB.y, 0.f);
            resB.z = fmaxf(rb[2] * scB + shB + xrB.z, 0.f);
            resB.w = fmaxf(rb[3] * scB + shB + xrB.w, 0.f);
            float* opA = out + (n * 64 + oa) * (T_ * V_) + t0 * V_ + col0;
            float* opB = out + (n * 64 + ob) * (T_ * V_) + t0 * V_ + col0;
            *reinterpret_cast<float4*>(opA) = resA;
            *reinterpret_cast<float4*>(opB) = resB;
        }
    }
}

extern "C" void kernel_launch(void* const* d_in, const int* in_sizes, int n_in,
                              void* d_out, int out_size)
{
    const float* x        = (const float*)d_in[0];
    const float* A        = (const float*)d_in[1];
    const float* GA       = (const float*)d_in[2];
    const float* g_w      = (const float*)d_in[3];
    const float* g_b      = (const float*)d_in[4];
    const float* a_w      = (const float*)d_in[5];
    const float* a_b      = (const float*)d_in[6];
    const float* b_w      = (const float*)d_in[7];
    const float* b_b      = (const float*)d_in[8];
    const float* bn_gamma = (const float*)d_in[9];
    const float* bn_beta  = (const float*)d_in[10];
    const float* bn_mean  = (const float*)d_in[11];
    const float* bn_var   = (const float*)d_in[12];
    float* out = (float*)d_out;

    size_t smemA = sizeof(SmemA);
    size_t smemB = sizeof(SmemB);
    cudaFuncSetAttribute(tsagc_attn_kernel,
                         cudaFuncAttributeMaxDynamicSharedMemorySize, (int)smemA);
    cudaFuncSetAttribute(tsagc_out_kernel,
                         cudaFuncAttributeMaxDynamicSharedMemorySize, (int)smemB);

    tsagc_attn_kernel<<<GRIDA_P, NTA, smemA>>>(x, A, GA, a_w, a_b, b_w, b_b);
    tsagc_out_kernel<<<GRIDB_P, NTB, smemB>>>(x, g_w, g_b, bn_gamma, bn_beta,
                                              bn_mean, bn_var, out);
}